// round 7
// baseline (speedup 1.0000x reference)
#include <cuda_runtime.h>
#include <cuda_bf16.h>
#include <cstdint>

#define NB 8
#define NH 16
#define SEQ 1024
#define DDIM 64
#define BM 128
#define BN 64
#define NTH 256

// SMEM: Q hi/lo (32KB) + 2 double-buffered K/V bf16 tile sets (32KB each)
#define SQH 0
#define SQL 16384
#define SBUF 32768
#define KVSTRIDE 32768
// within a buffer: KH +0, KL +8192, VH +16384, VL +24576
#define SMTOT (SBUF + 2 * KVSTRIDE)   // 98304

__device__ __forceinline__ uint32_t smem_u32(const void* p) {
    uint32_t a;
    asm("{ .reg .u64 t; cvta.to.shared.u64 t, %1; cvt.u32.u64 %0, t; }" : "=r"(a) : "l"(p));
    return a;
}
__device__ __forceinline__ uint32_t sw(uint32_t o) { return o ^ ((o >> 3) & 0x70); }

__device__ __forceinline__ void ldsm4(uint32_t& r0, uint32_t& r1, uint32_t& r2, uint32_t& r3,
                                      uint32_t a) {
    asm volatile("ldmatrix.sync.aligned.m8n8.x4.shared.b16 {%0,%1,%2,%3},[%4];"
                 : "=r"(r0), "=r"(r1), "=r"(r2), "=r"(r3) : "r"(a));
}
__device__ __forceinline__ void ldsm4t(uint32_t& r0, uint32_t& r1, uint32_t& r2, uint32_t& r3,
                                       uint32_t a) {
    asm volatile("ldmatrix.sync.aligned.m8n8.x4.trans.shared.b16 {%0,%1,%2,%3},[%4];"
                 : "=r"(r0), "=r"(r1), "=r"(r2), "=r"(r3) : "r"(a));
}
__device__ __forceinline__ void mma16816(float* c, uint32_t a0, uint32_t a1, uint32_t a2,
                                         uint32_t a3, uint32_t b0, uint32_t b1) {
    asm volatile("mma.sync.aligned.m16n8k16.row.col.f32.bf16.bf16.f32 "
                 "{%0,%1,%2,%3},{%4,%5,%6,%7},{%8,%9},{%0,%1,%2,%3};"
                 : "+f"(c[0]), "+f"(c[1]), "+f"(c[2]), "+f"(c[3])
                 : "r"(a0), "r"(a1), "r"(a2), "r"(a3), "r"(b0), "r"(b1));
}
// pack (x0,x1) -> bf16x2 hi part + bf16x2 residual part
__device__ __forceinline__ void split2(float x0, float x1, uint32_t& hi, uint32_t& lo) {
    uint32_t hh;
    asm("cvt.rn.bf16x2.f32 %0, %1, %2;" : "=r"(hh) : "f"(x1), "f"(x0));
    float h0 = __uint_as_float(hh << 16);
    float h1 = __uint_as_float(hh & 0xffff0000u);
    float l0 = x0 - h0, l1 = x1 - h1;
    uint32_t ll;
    asm("cvt.rn.bf16x2.f32 %0, %1, %2;" : "=r"(ll) : "f"(l1), "f"(l0));
    hi = hh; lo = ll;
}

__global__ __launch_bounds__(NTH)
void attn_mma(const float* __restrict__ q, const float* __restrict__ k,
              const float* __restrict__ v, const int* __restrict__ mask,
              const float* __restrict__ bias, float* __restrict__ out)
{
    extern __shared__ char smem[];
    __shared__ int s_len;
    const int tid  = threadIdx.x;
    const int lane = tid & 31;
    const int w    = tid >> 5;
    const int m0   = blockIdx.x * BM;
    const int h    = blockIdx.y;
    const int b    = blockIdx.z;
    const uint32_t sb = smem_u32(smem);

    if (tid == 0) s_len = 0;
    __syncthreads();
    {   // valid length (mask int32 0/1, monotone prefix)
        const int* mb = mask + (size_t)b * SEQ;
        int part = 0;
        for (int i = tid; i < SEQ; i += NTH) part += (mb[i] != 0);
        #pragma unroll
        for (int o = 16; o > 0; o >>= 1) part += __shfl_xor_sync(0xffffffffu, part, o);
        if (lane == 0) atomicAdd(&s_len, part);
    }

    // ---- Q tile fp32 -> bf16 hi/lo, swizzled [row][d] 128B rows ----
    {
        const int row = tid >> 1;
        const int cb  = (tid & 1) * 32;                 // float column base
        const uint32_t base = row * 128 + cb * 2;       // byte base (16B aligned)
        const float* qrow = q + (((size_t)b * NH + h) * SEQ + m0 + row) * DDIM + cb;
        #pragma unroll
        for (int c = 0; c < 4; c++) {                   // 4 chunks of 8 floats
            float4 t0 = *(const float4*)(qrow + 8 * c);
            float4 t1 = *(const float4*)(qrow + 8 * c + 4);
            uint4 hv, lv;
            split2(t0.x, t0.y, hv.x, lv.x);
            split2(t0.z, t0.w, hv.y, lv.y);
            split2(t1.x, t1.y, hv.z, lv.z);
            split2(t1.z, t1.w, hv.w, lv.w);
            uint32_t off = sw(base + 16 * c);
            *(uint4*)(smem + SQH + off) = hv;
            *(uint4*)(smem + SQL + off) = lv;
        }
    }
    __syncthreads();
    const int len = s_len;
    const int n_tiles = (len + BN - 1) / BN;

    // ldmatrix per-lane addressing pattern
    const int r8  = (lane & 7) + ((lane >> 3) & 1) * 8;
    const int c16 = ((lane >> 4) & 1) * 16;

    // ---- hoist Q fragments (tile-invariant) into registers ----
    uint32_t qh[4][4], ql[4][4];
    #pragma unroll
    for (int kbk = 0; kbk < 4; kbk++) {
        uint32_t off = sw((16 * w + r8) * 128 + 32 * kbk + c16);
        ldsm4(qh[kbk][0], qh[kbk][1], qh[kbk][2], qh[kbk][3], sb + SQH + off);
        ldsm4(ql[kbk][0], ql[kbk][1], ql[kbk][2], ql[kbk][3], sb + SQL + off);
    }

    float o[8][4];
    #pragma unroll
    for (int i = 0; i < 8; i++)
        #pragma unroll
        for (int j = 0; j < 4; j++) o[i][j] = 0.0f;
    float li1 = 0.0f, li2 = 0.0f;

    const float* kbp = k + (((size_t)b * NH + h) * SEQ) * DDIM;
    const float* vbp = v + (((size_t)b * NH + h) * SEQ) * DDIM;
    const float* bp1 = bias + ((size_t)h * SEQ + (m0 + 16 * w + (lane >> 2))) * SEQ;
    const float* bp2 = bp1 + 8 * SEQ;

    // per-thread K/V load slice: row kr, 16 floats from column cb
    const int kr = tid >> 2;
    const int cb = (tid & 3) * 16;
    const uint32_t kvbase = kr * 128 + cb * 2;   // byte base, 16B aligned

    // ---- prologue: prefetch tile 0 K/V fp32 into registers ----
    float4 pk[4], pv[4];
    {
        const float* krow = kbp + (size_t)kr * DDIM + cb;
        const float* vrow = vbp + (size_t)kr * DDIM + cb;
        #pragma unroll
        for (int i = 0; i < 4; i++) {
            pk[i] = *(const float4*)(krow + 4 * i);
            pv[i] = *(const float4*)(vrow + 4 * i);
        }
    }

    for (int t = 0; t < n_tiles; t++) {
        const int n0 = t * BN;
        char* bufp = smem + SBUF + (size_t)(t & 1) * KVSTRIDE;
        const uint32_t kvb = sb + SBUF + (uint32_t)(t & 1) * KVSTRIDE;

        // ---- convert prefetched K/V regs -> bf16 hi/lo (vectorized STS.128) ----
        #pragma unroll
        for (int c = 0; c < 2; c++) {                   // chunks: float4 pairs (2c, 2c+1)
            uint4 khv, klv, vhv, vlv;
            split2(pk[2 * c].x,     pk[2 * c].y,     khv.x, klv.x);
            split2(pk[2 * c].z,     pk[2 * c].w,     khv.y, klv.y);
            split2(pk[2 * c + 1].x, pk[2 * c + 1].y, khv.z, klv.z);
            split2(pk[2 * c + 1].z, pk[2 * c + 1].w, khv.w, klv.w);
            split2(pv[2 * c].x,     pv[2 * c].y,     vhv.x, vlv.x);
            split2(pv[2 * c].z,     pv[2 * c].w,     vhv.y, vlv.y);
            split2(pv[2 * c + 1].x, pv[2 * c + 1].y, vhv.z, vlv.z);
            split2(pv[2 * c + 1].z, pv[2 * c + 1].w, vhv.w, vlv.w);
            uint32_t off = sw(kvbase + 16 * c);
            *(uint4*)(bufp + 0     + off) = khv;
            *(uint4*)(bufp + 8192  + off) = klv;
            *(uint4*)(bufp + 16384 + off) = vhv;
            *(uint4*)(bufp + 24576 + off) = vlv;
        }
        __syncthreads();

        // ---- prefetch next tile's K/V (latency hidden under the GEMMs) ----
        if (t + 1 < n_tiles) {
            const float* krow = kbp + (size_t)((t + 1) * BN + kr) * DDIM + cb;
            const float* vrow = vbp + (size_t)((t + 1) * BN + kr) * DDIM + cb;
            #pragma unroll
            for (int i = 0; i < 4; i++) {
                pk[i] = *(const float4*)(krow + 4 * i);
                pv[i] = *(const float4*)(vrow + 4 * i);
            }
        }

        // ---- bias prefetch (overlaps GEMM1) ----
        float2 bb1[8], bb2[8];
        #pragma unroll
        for (int nb = 0; nb < 8; nb++) {
            int c = n0 + 8 * nb + (lane & 3) * 2;
            bb1[nb] = *(const float2*)(bp1 + c);
            bb2[nb] = *(const float2*)(bp2 + c);
        }

        // ---- GEMM1: S = QK^T, 3-way bf16 split; K frags loaded once ----
        float s[8][4];
        #pragma unroll
        for (int i = 0; i < 8; i++)
            #pragma unroll
            for (int j = 0; j < 4; j++) s[i][j] = 0.0f;
        #pragma unroll
        for (int kbk = 0; kbk < 4; kbk++) {
            #pragma unroll
            for (int nbp = 0; nbp < 4; nbp++) {
                uint32_t boff = sw((16 * nbp + r8) * 128 + 32 * kbk + c16);
                uint32_t bh0, bh1, bh2, bh3, bl0, bl1, bl2, bl3;
                ldsm4(bh0, bh1, bh2, bh3, kvb + boff);
                ldsm4(bl0, bl1, bl2, bl3, kvb + 8192 + boff);
                // hi*hi
                mma16816(s[2 * nbp],     qh[kbk][0], qh[kbk][1], qh[kbk][2], qh[kbk][3], bh0, bh2);
                mma16816(s[2 * nbp + 1], qh[kbk][0], qh[kbk][1], qh[kbk][2], qh[kbk][3], bh1, bh3);
                // lo*hi
                mma16816(s[2 * nbp],     ql[kbk][0], ql[kbk][1], ql[kbk][2], ql[kbk][3], bh0, bh2);
                mma16816(s[2 * nbp + 1], ql[kbk][0], ql[kbk][1], ql[kbk][2], ql[kbk][3], bh1, bh3);
                // hi*lo
                mma16816(s[2 * nbp],     qh[kbk][0], qh[kbk][1], qh[kbk][2], qh[kbk][3], bl0, bl2);
                mma16816(s[2 * nbp + 1], qh[kbk][0], qh[kbk][1], qh[kbk][2], qh[kbk][3], bl1, bl3);
            }
        }

        // ---- softmax (no max-sub), build P fragments in registers ----
        uint32_t pah[4][4], pal[4][4];
        #pragma unroll
        for (int nb = 0; nb < 8; nb++) {
            int n = n0 + 8 * nb + (lane & 3) * 2;
            float p0 = (n     < len) ? __expf(s[nb][0] + bb1[nb].x) : 0.0f;
            float p1 = (n + 1 < len) ? __expf(s[nb][1] + bb1[nb].y) : 0.0f;
            float p2 = (n     < len) ? __expf(s[nb][2] + bb2[nb].x) : 0.0f;
            float p3 = (n + 1 < len) ? __expf(s[nb][3] + bb2[nb].y) : 0.0f;
            li1 += p0 + p1;
            li2 += p2 + p3;
            split2(p0, p1, pah[nb >> 1][(nb & 1) * 2],     pal[nb >> 1][(nb & 1) * 2]);
            split2(p2, p3, pah[nb >> 1][(nb & 1) * 2 + 1], pal[nb >> 1][(nb & 1) * 2 + 1]);
        }

        // ---- GEMM2: O += P V, 3-way split (Ph*Vh, Pl*Vh, Ph*Vl) ----
        const uint32_t vh_ = kvb + 16384;
        const uint32_t vl_ = kvb + 24576;
        #pragma unroll
        for (int kbk = 0; kbk < 4; kbk++) {
            #pragma unroll
            for (int nbp = 0; nbp < 4; nbp++) {
                uint32_t voff = sw((16 * kbk + r8) * 128 + 32 * nbp + c16);
                uint32_t vh0, vh1, vh2, vh3;
                ldsm4t(vh0, vh1, vh2, vh3, vh_ + voff);
                mma16816(o[2 * nbp],     pah[kbk][0], pah[kbk][1], pah[kbk][2], pah[kbk][3], vh0, vh1);
                mma16816(o[2 * nbp + 1], pah[kbk][0], pah[kbk][1], pah[kbk][2], pah[kbk][3], vh2, vh3);
                mma16816(o[2 * nbp],     pal[kbk][0], pal[kbk][1], pal[kbk][2], pal[kbk][3], vh0, vh1);
                mma16816(o[2 * nbp + 1], pal[kbk][0], pal[kbk][1], pal[kbk][2], pal[kbk][3], vh2, vh3);
                uint32_t vl0, vl1, vl2, vl3;
                ldsm4t(vl0, vl1, vl2, vl3, vl_ + voff);
                mma16816(o[2 * nbp],     pah[kbk][0], pah[kbk][1], pah[kbk][2], pah[kbk][3], vl0, vl1);
                mma16816(o[2 * nbp + 1], pah[kbk][0], pah[kbk][1], pah[kbk][2], pah[kbk][3], vl2, vl3);
            }
        }
    }

    // ---- reduce li across the quad (lanes l^1, l^2 hold the same rows) ----
    li1 += __shfl_xor_sync(0xffffffffu, li1, 1);
    li1 += __shfl_xor_sync(0xffffffffu, li1, 2);
    li2 += __shfl_xor_sync(0xffffffffu, li2, 1);
    li2 += __shfl_xor_sync(0xffffffffu, li2, 2);

    // ---- epilogue: normalize, zero rows >= len, write [b, m, h*64+d] ----
    {
        const int r1 = 16 * w + (lane >> 2);
        const float inv1 = ((m0 + r1)     < len) ? (1.0f / li1) : 0.0f;
        const float inv2 = ((m0 + r1 + 8) < len) ? (1.0f / li2) : 0.0f;
        float* o1 = out + ((size_t)b * SEQ + m0 + r1) * (NH * DDIM) + (size_t)h * DDIM;
        float* o2 = o1 + 8 * (NH * DDIM);
        #pragma unroll
        for (int nb = 0; nb < 8; nb++) {
            int c = 8 * nb + (lane & 3) * 2;
            float2 w1 = {o[nb][0] * inv1, o[nb][1] * inv1};
            float2 w2 = {o[nb][2] * inv2, o[nb][3] * inv2};
            *(float2*)(o1 + c) = w1;
            *(float2*)(o2 + c) = w2;
        }
    }
}

extern "C" void kernel_launch(void* const* d_in, const int* in_sizes, int n_in,
                              void* d_out, int out_size)
{
    const float* q    = (const float*)d_in[0];
    const float* k    = (const float*)d_in[1];
    const float* v    = (const float*)d_in[2];
    const int*   mask = (const int*)d_in[3];
    const float* bias = (const float*)d_in[4];
    float* out = (float*)d_out;

    cudaFuncSetAttribute(attn_mma, cudaFuncAttributeMaxDynamicSharedMemorySize, SMTOT);
    dim3 grid(SEQ / BM, NH, NB);
    attn_mma<<<grid, NTH, SMTOT>>>(q, k, v, mask, bias, out);
}

// round 8
// speedup vs baseline: 1.2914x; 1.2914x over previous
#include <cuda_runtime.h>
#include <cuda_bf16.h>
#include <cstdint>

#define NB 8
#define NH 16
#define SEQ 1024
#define DDIM 64
#define BM 128
#define BN 64
#define NTH 512

// SMEM: Q hi/lo (32KB) + 2 double-buffered K/V bf16 tile sets (32KB each)
#define SQH 0
#define SQL 16384
#define SBUF 32768
#define KVSTRIDE 32768
// within a KV buffer: KH +0, KL +8192, VH +16384, VL +24576
#define SMTOT (SBUF + 2 * KVSTRIDE)   // 98304

__device__ __forceinline__ uint32_t smem_u32(const void* p) {
    uint32_t a;
    asm("{ .reg .u64 t; cvta.to.shared.u64 t, %1; cvt.u32.u64 %0, t; }" : "=r"(a) : "l"(p));
    return a;
}
__device__ __forceinline__ uint32_t sw(uint32_t o) { return o ^ ((o >> 3) & 0x70); }

__device__ __forceinline__ void ldsm4(uint32_t& r0, uint32_t& r1, uint32_t& r2, uint32_t& r3,
                                      uint32_t a) {
    asm volatile("ldmatrix.sync.aligned.m8n8.x4.shared.b16 {%0,%1,%2,%3},[%4];"
                 : "=r"(r0), "=r"(r1), "=r"(r2), "=r"(r3) : "r"(a));
}
__device__ __forceinline__ void ldsm4t(uint32_t& r0, uint32_t& r1, uint32_t& r2, uint32_t& r3,
                                       uint32_t a) {
    asm volatile("ldmatrix.sync.aligned.m8n8.x4.trans.shared.b16 {%0,%1,%2,%3},[%4];"
                 : "=r"(r0), "=r"(r1), "=r"(r2), "=r"(r3) : "r"(a));
}
__device__ __forceinline__ void mma16816(float* c, uint32_t a0, uint32_t a1, uint32_t a2,
                                         uint32_t a3, uint32_t b0, uint32_t b1) {
    asm volatile("mma.sync.aligned.m16n8k16.row.col.f32.bf16.bf16.f32 "
                 "{%0,%1,%2,%3},{%4,%5,%6,%7},{%8,%9},{%0,%1,%2,%3};"
                 : "+f"(c[0]), "+f"(c[1]), "+f"(c[2]), "+f"(c[3])
                 : "r"(a0), "r"(a1), "r"(a2), "r"(a3), "r"(b0), "r"(b1));
}
// pack (x0,x1) -> bf16x2 hi part + bf16x2 residual part
__device__ __forceinline__ void split2(float x0, float x1, uint32_t& hi, uint32_t& lo) {
    uint32_t hh;
    asm("cvt.rn.bf16x2.f32 %0, %1, %2;" : "=r"(hh) : "f"(x1), "f"(x0));
    float h0 = __uint_as_float(hh << 16);
    float h1 = __uint_as_float(hh & 0xffff0000u);
    float l0 = x0 - h0, l1 = x1 - h1;
    uint32_t ll;
    asm("cvt.rn.bf16x2.f32 %0, %1, %2;" : "=r"(ll) : "f"(l1), "f"(l0));
    hi = hh; lo = ll;
}

__global__ __launch_bounds__(NTH, 1)
void attn_mma(const float* __restrict__ q, const float* __restrict__ k,
              const float* __restrict__ v, const int* __restrict__ mask,
              const float* __restrict__ bias, float* __restrict__ out)
{
    extern __shared__ char smem[];
    __shared__ int s_len;
    __shared__ float s_li[2][128];
    const int tid  = threadIdx.x;
    const int lane = tid & 31;
    const int w    = tid >> 5;
    const int w_m  = w & 7;        // row group: rows 16*w_m .. +15
    const int w_n  = w >> 3;       // key half: keys 32*w_n .. +31 of each tile
    const int nh   = 32 * w_n;
    const int rowg = 16 * w_m;
    const int m0   = blockIdx.x * BM;
    const int h    = blockIdx.y;
    const int b    = blockIdx.z;
    const uint32_t sb = smem_u32(smem);

    if (tid == 0) s_len = 0;
    __syncthreads();
    {   // valid length (mask int32 0/1, monotone prefix)
        const int* mb = mask + (size_t)b * SEQ;
        int part = 0;
        for (int i = tid; i < SEQ; i += NTH) part += (mb[i] != 0);
        #pragma unroll
        for (int o = 16; o > 0; o >>= 1) part += __shfl_xor_sync(0xffffffffu, part, o);
        if (lane == 0) atomicAdd(&s_len, part);
    }

    // ---- Q tile fp32 -> bf16 hi/lo, swizzled [row][d] 128B rows ----
    {
        const int row  = tid >> 2;                 // 0..127
        const int colf = (tid & 3) * 16;           // float col base
        const float* qrow = q + (((size_t)b * NH + h) * SEQ + m0 + row) * DDIM + colf;
        #pragma unroll
        for (int c = 0; c < 2; c++) {              // 2 chunks of 8 floats
            float4 t0 = *(const float4*)(qrow + 8 * c);
            float4 t1 = *(const float4*)(qrow + 8 * c + 4);
            uint4 hv, lv;
            split2(t0.x, t0.y, hv.x, lv.x);
            split2(t0.z, t0.w, hv.y, lv.y);
            split2(t1.x, t1.y, hv.z, lv.z);
            split2(t1.z, t1.w, hv.w, lv.w);
            uint32_t off = sw(row * 128 + colf * 2 + 16 * c);
            *(uint4*)(smem + SQH + off) = hv;
            *(uint4*)(smem + SQL + off) = lv;
        }
    }
    __syncthreads();
    const int len = s_len;
    const int n_tiles = (len + BN - 1) / BN;

    // ldmatrix per-lane addressing pattern
    const int r8  = (lane & 7) + ((lane >> 3) & 1) * 8;
    const int c16 = ((lane >> 4) & 1) * 16;

    float o[8][4];
    #pragma unroll
    for (int i = 0; i < 8; i++)
        #pragma unroll
        for (int j = 0; j < 4; j++) o[i][j] = 0.0f;
    float li1 = 0.0f, li2 = 0.0f;

    const float* kbp = k + (((size_t)b * NH + h) * SEQ) * DDIM;
    const float* vbp = v + (((size_t)b * NH + h) * SEQ) * DDIM;
    const float* bp1 = bias + ((size_t)h * SEQ + (m0 + rowg + (lane >> 2))) * SEQ;
    const float* bp2 = bp1 + 8 * SEQ;

    // per-thread K/V load slice: row kr, 8 floats from column cf
    const int kr = tid >> 3;                  // 0..63
    const int cf = (tid & 7) * 8;             // 0..56
    const uint32_t kvbase = kr * 128 + cf * 2;   // 16B-aligned chunk

    // ---- prologue: prefetch tile 0 K/V fp32 into registers ----
    float4 pk[2], pv[2];
    {
        const float* krow = kbp + (size_t)kr * DDIM + cf;
        const float* vrow = vbp + (size_t)kr * DDIM + cf;
        pk[0] = *(const float4*)(krow);
        pk[1] = *(const float4*)(krow + 4);
        pv[0] = *(const float4*)(vrow);
        pv[1] = *(const float4*)(vrow + 4);
    }

    for (int t = 0; t < n_tiles; t++) {
        const int n0 = t * BN;
        char* bufp = smem + SBUF + (size_t)(t & 1) * KVSTRIDE;
        const uint32_t kvb = sb + SBUF + (uint32_t)(t & 1) * KVSTRIDE;

        // ---- convert prefetched K/V regs -> bf16 hi/lo (STS.128) ----
        {
            uint4 khv, klv, vhv, vlv;
            split2(pk[0].x, pk[0].y, khv.x, klv.x);
            split2(pk[0].z, pk[0].w, khv.y, klv.y);
            split2(pk[1].x, pk[1].y, khv.z, klv.z);
            split2(pk[1].z, pk[1].w, khv.w, klv.w);
            split2(pv[0].x, pv[0].y, vhv.x, vlv.x);
            split2(pv[0].z, pv[0].w, vhv.y, vlv.y);
            split2(pv[1].x, pv[1].y, vhv.z, vlv.z);
            split2(pv[1].z, pv[1].w, vhv.w, vlv.w);
            uint32_t off = sw(kvbase);
            *(uint4*)(bufp + 0     + off) = khv;
            *(uint4*)(bufp + 8192  + off) = klv;
            *(uint4*)(bufp + 16384 + off) = vhv;
            *(uint4*)(bufp + 24576 + off) = vlv;
        }
        __syncthreads();

        // ---- prefetch next tile's K/V (latency hidden under the GEMMs) ----
        if (t + 1 < n_tiles) {
            const float* krow = kbp + (size_t)((t + 1) * BN + kr) * DDIM + cf;
            const float* vrow = vbp + (size_t)((t + 1) * BN + kr) * DDIM + cf;
            pk[0] = *(const float4*)(krow);
            pk[1] = *(const float4*)(krow + 4);
            pv[0] = *(const float4*)(vrow);
            pv[1] = *(const float4*)(vrow + 4);
        }

        // ---- bias prefetch (overlaps GEMM1) ----
        float2 bb1[4], bb2[4];
        #pragma unroll
        for (int nb = 0; nb < 4; nb++) {
            int c = n0 + nh + 8 * nb + (lane & 3) * 2;
            bb1[nb] = *(const float2*)(bp1 + c);
            bb2[nb] = *(const float2*)(bp2 + c);
        }

        // ---- GEMM1: S = QK^T over this warp's 32-key half, 3-way split ----
        float s[4][4];
        #pragma unroll
        for (int i = 0; i < 4; i++)
            #pragma unroll
            for (int j = 0; j < 4; j++) s[i][j] = 0.0f;
        #pragma unroll
        for (int kbk = 0; kbk < 4; kbk++) {
            uint32_t qoff = sw((rowg + r8) * 128 + 32 * kbk + c16);
            uint32_t a0, a1, a2, a3, e0, e1, e2, e3;
            ldsm4(a0, a1, a2, a3, sb + SQH + qoff);
            ldsm4(e0, e1, e2, e3, sb + SQL + qoff);
            #pragma unroll
            for (int nbp = 0; nbp < 2; nbp++) {
                uint32_t boff = sw((nh + 16 * nbp + r8) * 128 + 32 * kbk + c16);
                uint32_t bh0, bh1, bh2, bh3;
                ldsm4(bh0, bh1, bh2, bh3, kvb + boff);
                mma16816(s[2 * nbp],     a0, a1, a2, a3, bh0, bh2);
                mma16816(s[2 * nbp + 1], a0, a1, a2, a3, bh1, bh3);
                mma16816(s[2 * nbp],     e0, e1, e2, e3, bh0, bh2);
                mma16816(s[2 * nbp + 1], e0, e1, e2, e3, bh1, bh3);
                uint32_t bl0, bl1, bl2, bl3;
                ldsm4(bl0, bl1, bl2, bl3, kvb + 8192 + boff);
                mma16816(s[2 * nbp],     a0, a1, a2, a3, bl0, bl2);
                mma16816(s[2 * nbp + 1], a0, a1, a2, a3, bl1, bl3);
            }
        }

        // ---- softmax (no max-sub), build P fragments in registers ----
        uint32_t pah[2][4], pal[2][4];
        #pragma unroll
        for (int nb = 0; nb < 4; nb++) {
            int n = n0 + nh + 8 * nb + (lane & 3) * 2;
            float p0 = (n     < len) ? __expf(s[nb][0] + bb1[nb].x) : 0.0f;
            float p1 = (n + 1 < len) ? __expf(s[nb][1] + bb1[nb].y) : 0.0f;
            float p2 = (n     < len) ? __expf(s[nb][2] + bb2[nb].x) : 0.0f;
            float p3 = (n + 1 < len) ? __expf(s[nb][3] + bb2[nb].y) : 0.0f;
            li1 += p0 + p1;
            li2 += p2 + p3;
            split2(p0, p1, pah[nb >> 1][(nb & 1) * 2],     pal[nb >> 1][(nb & 1) * 2]);
            split2(p2, p3, pah[nb >> 1][(nb & 1) * 2 + 1], pal[nb >> 1][(nb & 1) * 2 + 1]);
        }

        // ---- GEMM2: O(partial) += P V over this warp's 32 keys ----
        const uint32_t vh_ = kvb + 16384;
        const uint32_t vl_ = kvb + 24576;
        #pragma unroll
        for (int kk = 0; kk < 2; kk++) {
            #pragma unroll
            for (int nbp = 0; nbp < 4; nbp++) {
                uint32_t voff = sw((nh + 16 * kk + r8) * 128 + 32 * nbp + c16);
                uint32_t vh0, vh1, vh2, vh3;
                ldsm4t(vh0, vh1, vh2, vh3, vh_ + voff);
                mma16816(o[2 * nbp],     pah[kk][0], pah[kk][1], pah[kk][2], pah[kk][3], vh0, vh1);
                mma16816(o[2 * nbp + 1], pah[kk][0], pah[kk][1], pah[kk][2], pah[kk][3], vh2, vh3);
                mma16816(o[2 * nbp],     pal[kk][0], pal[kk][1], pal[kk][2], pal[kk][3], vh0, vh1);
                mma16816(o[2 * nbp + 1], pal[kk][0], pal[kk][1], pal[kk][2], pal[kk][3], vh2, vh3);
                uint32_t vl0, vl1, vl2, vl3;
                ldsm4t(vl0, vl1, vl2, vl3, vl_ + voff);
                mma16816(o[2 * nbp],     pah[kk][0], pah[kk][1], pah[kk][2], pah[kk][3], vl0, vl1);
                mma16816(o[2 * nbp + 1], pah[kk][0], pah[kk][1], pah[kk][2], pah[kk][3], vl2, vl3);
            }
        }
    }

    // ---- reduce li across the quad (lanes l^1, l^2 hold the same rows) ----
    li1 += __shfl_xor_sync(0xffffffffu, li1, 1);
    li1 += __shfl_xor_sync(0xffffffffu, li1, 2);
    li2 += __shfl_xor_sync(0xffffffffu, li2, 1);
    li2 += __shfl_xor_sync(0xffffffffu, li2, 2);

    // ---- combine the two key-halves: O(partial) and li through smem ----
    __syncthreads();   // all GEMM2 smem reads done; safe to alias KV buffer 0
    float* oshare = (float*)(smem + SBUF);   // [128][64] fp32 = 32KB
    const int r1 = rowg + (lane >> 2);
    if (w_n == 1) {
        #pragma unroll
        for (int nb = 0; nb < 8; nb++) {
            int c = 8 * nb + (lane & 3) * 2;
            *(float2*)(oshare + r1 * 64 + c)       = make_float2(o[nb][0], o[nb][1]);
            *(float2*)(oshare + (r1 + 8) * 64 + c) = make_float2(o[nb][2], o[nb][3]);
        }
        if ((lane & 3) == 0) {
            s_li[1][r1]     = li1;
            s_li[1][r1 + 8] = li2;
        }
    }
    __syncthreads();

    if (w_n == 0) {
        const float lt1 = li1 + s_li[1][r1];
        const float lt2 = li2 + s_li[1][r1 + 8];
        const float inv1 = ((m0 + r1)     < len) ? (1.0f / lt1) : 0.0f;
        const float inv2 = ((m0 + r1 + 8) < len) ? (1.0f / lt2) : 0.0f;
        float* o1 = out + ((size_t)b * SEQ + m0 + r1) * (NH * DDIM) + (size_t)h * DDIM;
        float* o2 = o1 + 8 * (NH * DDIM);
        #pragma unroll
        for (int nb = 0; nb < 8; nb++) {
            int c = 8 * nb + (lane & 3) * 2;
            float2 q1 = *(const float2*)(oshare + r1 * 64 + c);
            float2 q2 = *(const float2*)(oshare + (r1 + 8) * 64 + c);
            float2 w1 = {(o[nb][0] + q1.x) * inv1, (o[nb][1] + q1.y) * inv1};
            float2 w2 = {(o[nb][2] + q2.x) * inv2, (o[nb][3] + q2.y) * inv2};
            *(float2*)(o1 + c) = w1;
            *(float2*)(o2 + c) = w2;
        }
    }
}

extern "C" void kernel_launch(void* const* d_in, const int* in_sizes, int n_in,
                              void* d_out, int out_size)
{
    const float* q    = (const float*)d_in[0];
    const float* k    = (const float*)d_in[1];
    const float* v    = (const float*)d_in[2];
    const int*   mask = (const int*)d_in[3];
    const float* bias = (const float*)d_in[4];
    float* out = (float*)d_out;

    cudaFuncSetAttribute(attn_mma, cudaFuncAttributeMaxDynamicSharedMemorySize, SMTOT);
    dim3 grid(SEQ / BM, NH, NB);
    attn_mma<<<grid, NTH, SMTOT>>>(q, k, v, mask, bias, out);
}

// round 9
// speedup vs baseline: 1.3308x; 1.0304x over previous
#include <cuda_runtime.h>
#include <cuda_bf16.h>
#include <cstdint>

#define NB 8
#define NH 16
#define SEQ 1024
#define DDIM 64
#define BM 128
#define BN 64
#define NTH 512
#define LOG2E 1.4426950408889634f

// SMEM: Q hi/lo (32KB) + 2 double-buffered K/V bf16 tile sets (32KB each)
#define SQH 0
#define SQL 16384
#define SBUF 32768
#define KVSTRIDE 32768
// within a KV buffer: KH +0, KL +8192, VH +16384, VL +24576
#define SMTOT (SBUF + 2 * KVSTRIDE)   // 98304

__device__ __forceinline__ uint32_t smem_u32(const void* p) {
    uint32_t a;
    asm("{ .reg .u64 t; cvta.to.shared.u64 t, %1; cvt.u32.u64 %0, t; }" : "=r"(a) : "l"(p));
    return a;
}
__device__ __forceinline__ uint32_t sw(uint32_t o) { return o ^ ((o >> 3) & 0x70); }

__device__ __forceinline__ void ldsm4(uint32_t& r0, uint32_t& r1, uint32_t& r2, uint32_t& r3,
                                      uint32_t a) {
    asm volatile("ldmatrix.sync.aligned.m8n8.x4.shared.b16 {%0,%1,%2,%3},[%4];"
                 : "=r"(r0), "=r"(r1), "=r"(r2), "=r"(r3) : "r"(a));
}
__device__ __forceinline__ void ldsm4t(uint32_t& r0, uint32_t& r1, uint32_t& r2, uint32_t& r3,
                                       uint32_t a) {
    asm volatile("ldmatrix.sync.aligned.m8n8.x4.trans.shared.b16 {%0,%1,%2,%3},[%4];"
                 : "=r"(r0), "=r"(r1), "=r"(r2), "=r"(r3) : "r"(a));
}
__device__ __forceinline__ void mma16816(float* c, uint32_t a0, uint32_t a1, uint32_t a2,
                                         uint32_t a3, uint32_t b0, uint32_t b1) {
    asm volatile("mma.sync.aligned.m16n8k16.row.col.f32.bf16.bf16.f32 "
                 "{%0,%1,%2,%3},{%4,%5,%6,%7},{%8,%9},{%0,%1,%2,%3};"
                 : "+f"(c[0]), "+f"(c[1]), "+f"(c[2]), "+f"(c[3])
                 : "r"(a0), "r"(a1), "r"(a2), "r"(a3), "r"(b0), "r"(b1));
}
// pack (x0,x1) -> bf16x2 hi part + bf16x2 residual part
__device__ __forceinline__ void split2(float x0, float x1, uint32_t& hi, uint32_t& lo) {
    uint32_t hh;
    asm("cvt.rn.bf16x2.f32 %0, %1, %2;" : "=r"(hh) : "f"(x1), "f"(x0));
    float h0 = __uint_as_float(hh << 16);
    float h1 = __uint_as_float(hh & 0xffff0000u);
    float l0 = x0 - h0, l1 = x1 - h1;
    uint32_t ll;
    asm("cvt.rn.bf16x2.f32 %0, %1, %2;" : "=r"(ll) : "f"(l1), "f"(l0));
    hi = hh; lo = ll;
}

__global__ __launch_bounds__(NTH, 1)
void attn_mma(const float* __restrict__ q, const float* __restrict__ k,
              const float* __restrict__ v, const int* __restrict__ mask,
              const float* __restrict__ bias, float* __restrict__ out)
{
    extern __shared__ char smem[];
    __shared__ int s_len;
    __shared__ float s_li[2][128];
    const int tid  = threadIdx.x;
    const int lane = tid & 31;
    const int w    = tid >> 5;
    const int w_m  = w & 7;        // row group: rows 16*w_m .. +15
    const int w_n  = w >> 3;       // key half: keys 32*w_n .. +31 of each tile
    const int nh   = 32 * w_n;
    const int rowg = 16 * w_m;
    const int m0   = blockIdx.x * BM;
    const int h    = blockIdx.y;
    const int b    = blockIdx.z;
    const uint32_t sb = smem_u32(smem);

    if (tid == 0) s_len = 0;
    __syncthreads();
    {   // valid length (mask int32 0/1, monotone prefix)
        const int* mb = mask + (size_t)b * SEQ;
        int part = 0;
        for (int i = tid; i < SEQ; i += NTH) part += (mb[i] != 0);
        #pragma unroll
        for (int o = 16; o > 0; o >>= 1) part += __shfl_xor_sync(0xffffffffu, part, o);
        if (lane == 0) atomicAdd(&s_len, part);
    }

    // ---- Q tile fp32 -> bf16 hi/lo, swizzled [row][d] 128B rows ----
    {
        const int row  = tid >> 2;                 // 0..127
        const int colf = (tid & 3) * 16;           // float col base
        const float* qrow = q + (((size_t)b * NH + h) * SEQ + m0 + row) * DDIM + colf;
        #pragma unroll
        for (int c = 0; c < 2; c++) {              // 2 chunks of 8 floats
            float4 t0 = *(const float4*)(qrow + 8 * c);
            float4 t1 = *(const float4*)(qrow + 8 * c + 4);
            uint4 hv, lv;
            split2(t0.x, t0.y, hv.x, lv.x);
            split2(t0.z, t0.w, hv.y, lv.y);
            split2(t1.x, t1.y, hv.z, lv.z);
            split2(t1.z, t1.w, hv.w, lv.w);
            uint32_t off = sw(row * 128 + colf * 2 + 16 * c);
            *(uint4*)(smem + SQH + off) = hv;
            *(uint4*)(smem + SQL + off) = lv;
        }
    }
    __syncthreads();
    const int len = s_len;
    const int n_tiles = (len + BN - 1) / BN;

    // ldmatrix per-lane addressing pattern
    const int r8  = (lane & 7) + ((lane >> 3) & 1) * 8;
    const int c16 = ((lane >> 4) & 1) * 16;

    float o[8][4];
    #pragma unroll
    for (int i = 0; i < 8; i++)
        #pragma unroll
        for (int j = 0; j < 4; j++) o[i][j] = 0.0f;
    float li1 = 0.0f, li2 = 0.0f;

    const float* kbp = k + (((size_t)b * NH + h) * SEQ) * DDIM;
    const float* vbp = v + (((size_t)b * NH + h) * SEQ) * DDIM;
    const float* bp1 = bias + ((size_t)h * SEQ + (m0 + rowg + (lane >> 2))) * SEQ;
    const float* bp2 = bp1 + 8 * SEQ;

    // per-thread K/V conversion slice: this half converts ONLY its own 32 rows
    // [nh, nh+32) — the rows its warps read in GEMM1/GEMM2. Each half syncs on
    // its own named barrier, decoupling the two halves in time.
    const int g  = tid & 255;                 // id within the 256-thread half
    const int kr = nh + (g >> 3);             // row within tile (nh..nh+31)
    const int cf = (g & 7) * 8;               // float col base
    const uint32_t kvbase = kr * 128 + cf * 2;   // 16B-aligned chunk

    // ---- prologue: prefetch tile 0 K/V fp32 into registers ----
    float4 pk[2], pv[2];
    {
        const float* krow = kbp + (size_t)kr * DDIM + cf;
        const float* vrow = vbp + (size_t)kr * DDIM + cf;
        pk[0] = *(const float4*)(krow);
        pk[1] = *(const float4*)(krow + 4);
        pv[0] = *(const float4*)(vrow);
        pv[1] = *(const float4*)(vrow + 4);
    }

    for (int t = 0; t < n_tiles; t++) {
        const int n0 = t * BN;
        char* bufp = smem + SBUF + (size_t)(t & 1) * KVSTRIDE;
        const uint32_t kvb = sb + SBUF + (uint32_t)(t & 1) * KVSTRIDE;

        // ---- convert prefetched K/V regs -> bf16 hi/lo (STS.128) ----
        {
            uint4 khv, klv, vhv, vlv;
            split2(pk[0].x, pk[0].y, khv.x, klv.x);
            split2(pk[0].z, pk[0].w, khv.y, klv.y);
            split2(pk[1].x, pk[1].y, khv.z, klv.z);
            split2(pk[1].z, pk[1].w, khv.w, klv.w);
            split2(pv[0].x, pv[0].y, vhv.x, vlv.x);
            split2(pv[0].z, pv[0].w, vhv.y, vlv.y);
            split2(pv[1].x, pv[1].y, vhv.z, vlv.z);
            split2(pv[1].z, pv[1].w, vhv.w, vlv.w);
            uint32_t off = sw(kvbase);
            *(uint4*)(bufp + 0     + off) = khv;
            *(uint4*)(bufp + 8192  + off) = klv;
            *(uint4*)(bufp + 16384 + off) = vhv;
            *(uint4*)(bufp + 24576 + off) = vlv;
        }

        // ---- prefetch next tile's K/V (issue before the barrier) ----
        if (t + 1 < n_tiles) {
            const float* krow = kbp + (size_t)((t + 1) * BN + kr) * DDIM + cf;
            const float* vrow = vbp + (size_t)((t + 1) * BN + kr) * DDIM + cf;
            pk[0] = *(const float4*)(krow);
            pk[1] = *(const float4*)(krow + 4);
            pv[0] = *(const float4*)(vrow);
            pv[1] = *(const float4*)(vrow + 4);
        }

        // ---- bias prefetch (pre-scaled by log2(e); overlaps GEMM1) ----
        float2 bb1[4], bb2[4];
        #pragma unroll
        for (int nb = 0; nb < 4; nb++) {
            int c = n0 + nh + 8 * nb + (lane & 3) * 2;
            bb1[nb] = *(const float2*)(bp1 + c);
            bb2[nb] = *(const float2*)(bp2 + c);
            bb1[nb].x *= LOG2E; bb1[nb].y *= LOG2E;
            bb2[nb].x *= LOG2E; bb2[nb].y *= LOG2E;
        }

        // ---- half-CTA barrier: this half's conversion visible to its warps ----
        asm volatile("bar.sync %0, 256;" :: "r"(1 + w_n) : "memory");

        // ---- GEMM1: S = QK^T over this warp's 32-key half, 3-way split ----
        float s[4][4];
        #pragma unroll
        for (int i = 0; i < 4; i++)
            #pragma unroll
            for (int j = 0; j < 4; j++) s[i][j] = 0.0f;
        #pragma unroll
        for (int kbk = 0; kbk < 4; kbk++) {
            uint32_t qoff = sw((rowg + r8) * 128 + 32 * kbk + c16);
            uint32_t a0, a1, a2, a3, e0, e1, e2, e3;
            ldsm4(a0, a1, a2, a3, sb + SQH + qoff);
            ldsm4(e0, e1, e2, e3, sb + SQL + qoff);
            #pragma unroll
            for (int nbp = 0; nbp < 2; nbp++) {
                uint32_t boff = sw((nh + 16 * nbp + r8) * 128 + 32 * kbk + c16);
                uint32_t bh0, bh1, bh2, bh3, bl0, bl1, bl2, bl3;
                ldsm4(bh0, bh1, bh2, bh3, kvb + boff);
                ldsm4(bl0, bl1, bl2, bl3, kvb + 8192 + boff);
                mma16816(s[2 * nbp],     a0, a1, a2, a3, bh0, bh2);
                mma16816(s[2 * nbp + 1], a0, a1, a2, a3, bh1, bh3);
                mma16816(s[2 * nbp],     e0, e1, e2, e3, bh0, bh2);
                mma16816(s[2 * nbp + 1], e0, e1, e2, e3, bh1, bh3);
                mma16816(s[2 * nbp],     a0, a1, a2, a3, bl0, bl2);
                mma16816(s[2 * nbp + 1], a0, a1, a2, a3, bl1, bl3);
            }
        }

        // ---- softmax: p = exp2(s*log2e + bias*log2e), no max-sub ----
        uint32_t pah[2][4], pal[2][4];
        #pragma unroll
        for (int nb = 0; nb < 4; nb++) {
            int n = n0 + nh + 8 * nb + (lane & 3) * 2;
            float p0 = (n     < len) ? exp2f(fmaf(s[nb][0], LOG2E, bb1[nb].x)) : 0.0f;
            float p1 = (n + 1 < len) ? exp2f(fmaf(s[nb][1], LOG2E, bb1[nb].y)) : 0.0f;
            float p2 = (n     < len) ? exp2f(fmaf(s[nb][2], LOG2E, bb2[nb].x)) : 0.0f;
            float p3 = (n + 1 < len) ? exp2f(fmaf(s[nb][3], LOG2E, bb2[nb].y)) : 0.0f;
            li1 += p0 + p1;
            li2 += p2 + p3;
            split2(p0, p1, pah[nb >> 1][(nb & 1) * 2],     pal[nb >> 1][(nb & 1) * 2]);
            split2(p2, p3, pah[nb >> 1][(nb & 1) * 2 + 1], pal[nb >> 1][(nb & 1) * 2 + 1]);
        }

        // ---- GEMM2: O(partial) += P V over this warp's 32 keys ----
        const uint32_t vh_ = kvb + 16384;
        const uint32_t vl_ = kvb + 24576;
        #pragma unroll
        for (int kk = 0; kk < 2; kk++) {
            #pragma unroll
            for (int nbp = 0; nbp < 4; nbp++) {
                uint32_t voff = sw((nh + 16 * kk + r8) * 128 + 32 * nbp + c16);
                uint32_t vh0, vh1, vh2, vh3, vl0, vl1, vl2, vl3;
                ldsm4t(vh0, vh1, vh2, vh3, vh_ + voff);
                ldsm4t(vl0, vl1, vl2, vl3, vl_ + voff);
                mma16816(o[2 * nbp],     pah[kk][0], pah[kk][1], pah[kk][2], pah[kk][3], vh0, vh1);
                mma16816(o[2 * nbp + 1], pah[kk][0], pah[kk][1], pah[kk][2], pah[kk][3], vh2, vh3);
                mma16816(o[2 * nbp],     pal[kk][0], pal[kk][1], pal[kk][2], pal[kk][3], vh0, vh1);
                mma16816(o[2 * nbp + 1], pal[kk][0], pal[kk][1], pal[kk][2], pal[kk][3], vh2, vh3);
                mma16816(o[2 * nbp],     pah[kk][0], pah[kk][1], pah[kk][2], pah[kk][3], vl0, vl1);
                mma16816(o[2 * nbp + 1], pah[kk][0], pah[kk][1], pah[kk][2], pah[kk][3], vl2, vl3);
            }
        }
    }

    // ---- reduce li across the quad (lanes l^1, l^2 hold the same rows) ----
    li1 += __shfl_xor_sync(0xffffffffu, li1, 1);
    li1 += __shfl_xor_sync(0xffffffffu, li1, 2);
    li2 += __shfl_xor_sync(0xffffffffu, li2, 1);
    li2 += __shfl_xor_sync(0xffffffffu, li2, 2);

    // ---- combine the two key-halves: O(partial) and li through smem ----
    __syncthreads();   // all GEMM2 smem reads done; safe to alias KV buffer 0
    float* oshare = (float*)(smem + SBUF);   // [128][64] fp32 = 32KB
    const int r1 = rowg + (lane >> 2);
    if (w_n == 1) {
        #pragma unroll
        for (int nb = 0; nb < 8; nb++) {
            int c = 8 * nb + (lane & 3) * 2;
            *(float2*)(oshare + r1 * 64 + c)       = make_float2(o[nb][0], o[nb][1]);
            *(float2*)(oshare + (r1 + 8) * 64 + c) = make_float2(o[nb][2], o[nb][3]);
        }
        if ((lane & 3) == 0) {
            s_li[1][r1]     = li1;
            s_li[1][r1 + 8] = li2;
        }
    }
    __syncthreads();

    if (w_n == 0) {
        const float lt1 = li1 + s_li[1][r1];
        const float lt2 = li2 + s_li[1][r1 + 8];
        const float inv1 = ((m0 + r1)     < len) ? (1.0f / lt1) : 0.0f;
        const float inv2 = ((m0 + r1 + 8) < len) ? (1.0f / lt2) : 0.0f;
        float* o1 = out + ((size_t)b * SEQ + m0 + r1) * (NH * DDIM) + (size_t)h * DDIM;
        float* o2 = o1 + 8 * (NH * DDIM);
        #pragma unroll
        for (int nb = 0; nb < 8; nb++) {
            int c = 8 * nb + (lane & 3) * 2;
            float2 q1 = *(const float2*)(oshare + r1 * 64 + c);
            float2 q2 = *(const float2*)(oshare + (r1 + 8) * 64 + c);
            float2 w1 = {(o[nb][0] + q1.x) * inv1, (o[nb][1] + q1.y) * inv1};
            float2 w2 = {(o[nb][2] + q2.x) * inv2, (o[nb][3] + q2.y) * inv2};
            *(float2*)(o1 + c) = w1;
            *(float2*)(o2 + c) = w2;
        }
    }
}

extern "C" void kernel_launch(void* const* d_in, const int* in_sizes, int n_in,
                              void* d_out, int out_size)
{
    const float* q    = (const float*)d_in[0];
    const float* k    = (const float*)d_in[1];
    const float* v    = (const float*)d_in[2];
    const int*   mask = (const int*)d_in[3];
    const float* bias = (const float*)d_in[4];
    float* out = (float*)d_out;

    cudaFuncSetAttribute(attn_mma, cudaFuncAttributeMaxDynamicSharedMemorySize, SMTOT);
    dim3 grid(SEQ / BM, NH, NB);
    attn_mma<<<grid, NTH, SMTOT>>>(q, k, v, mask, bias, out);
}